// round 14
// baseline (speedup 1.0000x reference)
#include <cuda_runtime.h>
#include <cuda_fp16.h>
#include <cstdint>

// ---------------------------------------------------------------------------
// Split-fp16 global tensors (static device memory — no cudaMalloc anywhere)
// ---------------------------------------------------------------------------
__device__ __half g_xh [4096u * 1024u];
__device__ __half g_xl [4096u * 1024u];
__device__ uint32_t g_wq_h [512u * 1024u];   // pre-paired across k: u32 = {w[2k],w[2k+1]}
__device__ uint32_t g_wq_l [512u * 1024u];
__device__ uint32_t g_wvk_h[512u * 2048u];
__device__ uint32_t g_wvk_l[512u * 2048u];
__device__ uint32_t g_wo_h [512u * 1024u];
__device__ uint32_t g_wo_l [512u * 1024u];
__device__ __half g_qh [4096u * 1024u];
__device__ __half g_ql [4096u * 1024u];
__device__ __half g_kvh[4096u * 2048u];
__device__ __half g_kvl[4096u * 2048u];
__device__ __half g_aoh[4096u * 1024u];
__device__ __half g_aol[4096u * 1024u];

// ---------------------------------------------------------------------------
// helpers
// ---------------------------------------------------------------------------
// Markidis split of (x0,x1) into packed half2 hi/lo; x0 in LOW half.
__device__ __forceinline__ void f16_split2(float x0, float x1, uint32_t& hi, uint32_t& lo) {
    __half2 h = __floats2half2_rn(x0, x1);
    __half2 l = __floats2half2_rn(x0 - __low2float(h), x1 - __high2float(h));
    hi = *reinterpret_cast<uint32_t*>(&h);
    lo = *reinterpret_cast<uint32_t*>(&l);
}
// fp16 m16n8k16 (validated): A a0=(g,2t|2t+1) a1=(g+8,..) a2=(g,2t+8|2t+9) a3=(g+8,..)
// B b0=(2t|2t+1, g) b1=(2t+8|2t+9, g); C c0=(g,2t) c1=(g,2t+1) c2=(g+8,2t) c3=(g+8,2t+1)
__device__ __forceinline__ void mma_f16(float c[4], const uint32_t a[4], const uint32_t b[2]) {
    asm volatile(
        "mma.sync.aligned.m16n8k16.row.col.f32.f16.f16.f32 "
        "{%0,%1,%2,%3}, {%4,%5,%6,%7}, {%8,%9}, {%0,%1,%2,%3};\n"
        : "+f"(c[0]), "+f"(c[1]), "+f"(c[2]), "+f"(c[3])
        : "r"(a[0]), "r"(a[1]), "r"(a[2]), "r"(a[3]), "r"(b[0]), "r"(b[1]));
}
__device__ __forceinline__ void mma3_f16(float c[4], const uint32_t ah[4], const uint32_t al[4],
                                         const uint32_t bh[2], const uint32_t bl[2]) {
    mma_f16(c, ah, bl);
    mma_f16(c, al, bh);
    mma_f16(c, ah, bh);
}
__device__ __forceinline__ uint32_t smem_u32(const void* p) {
    return (uint32_t)__cvta_generic_to_shared(p);
}
__device__ __forceinline__ void cp16(uint32_t saddr, const void* gptr) {
    asm volatile("cp.async.cg.shared.global [%0], [%1], 16;\n" :: "r"(saddr), "l"(gptr));
}
#define CP_COMMIT() asm volatile("cp.async.commit_group;\n" ::: "memory")
#define CP_WAIT0()  asm volatile("cp.async.wait_group 0;\n" ::: "memory")
#define CP_WAIT1()  asm volatile("cp.async.wait_group 1;\n" ::: "memory")

// ---------------------------------------------------------------------------
// presplit kernels (run once; pure bandwidth)
// ---------------------------------------------------------------------------
__global__ void presplit_plain(const float* __restrict__ x, __half* __restrict__ xh,
                               __half* __restrict__ xl, int n) {
    int i = (blockIdx.x * blockDim.x + threadIdx.x) * 4;
    if (i >= n) return;
    float4 v = *reinterpret_cast<const float4*>(x + i);
    uint32_t h0, l0, h1, l1;
    f16_split2(v.x, v.y, h0, l0);
    f16_split2(v.z, v.w, h1, l1);
    *reinterpret_cast<uint2*>(xh + i) = make_uint2(h0, h1);
    *reinterpret_cast<uint2*>(xl + i) = make_uint2(l0, l1);
}

// w [K][N] f32 -> u32 [K/2][N] pairs across k (low half = lower k)
__global__ void presplit_wpair(const float* __restrict__ w, uint32_t* __restrict__ wh,
                               uint32_t* __restrict__ wl, int K, int N) {
    int idx = blockIdx.x * blockDim.x + threadIdx.x;   // over (K/2)*(N/4)
    int kp = idx / (N >> 2);
    int n4 = (idx % (N >> 2)) * 4;
    if (kp >= (K >> 1)) return;
    const float* r0 = w + (size_t)(2 * kp) * N + n4;
    float4 a = *reinterpret_cast<const float4*>(r0);
    float4 b = *reinterpret_cast<const float4*>(r0 + N);
    uint32_t h[4], l[4];
    f16_split2(a.x, b.x, h[0], l[0]);
    f16_split2(a.y, b.y, h[1], l[1]);
    f16_split2(a.z, b.z, h[2], l[2]);
    f16_split2(a.w, b.w, h[3], l[3]);
    *reinterpret_cast<uint4*>(wh + (size_t)kp * N + n4) = make_uint4(h[0], h[1], h[2], h[3]);
    *reinterpret_cast<uint4*>(wl + (size_t)kp * N + n4) = make_uint4(l[0], l[1], l[2], l[3]);
}

// ---------------------------------------------------------------------------
// split-fp16 GEMM, pre-split inputs, DOUBLE-BUFFERED cp.async staging.
// C[M,N] = A[M,K] @ B[K,N]. A: row-major half hi/lo. B: pre-paired u32 [K/2][N].
// Block 128x128, BK=32, 256 thr (8 warps 2m x 4n), warp tile 64x32.
// mode 0: C fp32;  mode 1: C split-fp16 (Ch/Cl).
// Dynamic smem: 2 stages x {Ah2/Al2 [128][20], Bh2/Bl2 [16][136]} = 75776 B.
// ---------------------------------------------------------------------------
#define GAH (128 * 20)
#define GBH (16 * 136)
#define GSTG (2 * GAH + 2 * GBH)          // 9472 u32 per stage
#define GEMM_SMEM (2 * GSTG * 4)          // 75776 bytes

__global__ void __launch_bounds__(256, 2)
gemm_f16p_kernel(const __half* __restrict__ Ah_g, const __half* __restrict__ Al_g,
                 const uint32_t* __restrict__ Bh_g, const uint32_t* __restrict__ Bl_g,
                 float* __restrict__ Cf, __half* __restrict__ Ch, __half* __restrict__ Cl,
                 int M, int N, int K, int mode) {
    extern __shared__ uint32_t sm[];
    const uint32_t sbase = smem_u32(sm);

    const int tid  = threadIdx.x;
    const int lane = tid & 31;
    const int warp = tid >> 5;
    const int g = lane >> 2;
    const int t = lane & 3;
    const int wm = warp >> 2;
    const int wn = warp & 3;
    const int bm = blockIdx.y * 128;
    const int bn = blockIdx.x * 128;

    float acc[4][4][4];
#pragma unroll
    for (int i = 0; i < 4; i++)
#pragma unroll
        for (int j = 0; j < 4; j++)
#pragma unroll
            for (int v = 0; v < 4; v++) acc[i][j][v] = 0.f;

    // cp.async one fp16 k-stage into buffer s
    auto load_stage = [&](int k0, int s) {
        uint32_t ah_s = sbase + (uint32_t)(s * GSTG) * 4u;
        uint32_t al_s = ah_s + (uint32_t)GAH * 4u;
        uint32_t bh_s = al_s + (uint32_t)GAH * 4u;
        uint32_t bl_s = bh_s + (uint32_t)GBH * 4u;
#pragma unroll
        for (int p = 0; p < 2; p++) {
            int idx = tid + p * 256;           // 512 chunks per A buffer
            int r  = idx >> 2;
            int cu = (idx & 3) << 2;           // u32 offset in row (0,4,8,12)
            cp16(ah_s + (uint32_t)(r * 20 + cu) * 4u,
                 Ah_g + (size_t)(bm + r) * K + k0 + cu * 2);
            cp16(al_s + (uint32_t)(r * 20 + cu) * 4u,
                 Al_g + (size_t)(bm + r) * K + k0 + cu * 2);
        }
#pragma unroll
        for (int p = 0; p < 2; p++) {
            int idx = tid + p * 256;           // 512 chunks per B buffer
            int kp = idx >> 5;
            int cu = (idx & 31) << 2;
            cp16(bh_s + (uint32_t)(kp * 136 + cu) * 4u,
                 Bh_g + (size_t)((k0 >> 1) + kp) * N + bn + cu);
            cp16(bl_s + (uint32_t)(kp * 136 + cu) * 4u,
                 Bl_g + (size_t)((k0 >> 1) + kp) * N + bn + cu);
        }
    };

    const int nk = K / 32;
    load_stage(0, 0);  CP_COMMIT();
    load_stage(32, 1); CP_COMMIT();
    CP_WAIT1();            // stage 0 complete
    __syncthreads();

    for (int i = 0; i < nk; i++) {
        const uint32_t* Ah2 = sm + (i & 1) * GSTG;
        const uint32_t* Al2 = Ah2 + GAH;
        const uint32_t* Bh2 = Al2 + GAH;
        const uint32_t* Bl2 = Bh2 + GBH;

        // ---- MMA phase (validated indexing) ----
#pragma unroll
        for (int ks = 0; ks < 2; ks++) {
            const int kb2 = ks * 8;
            uint32_t afh[4][4], afl[4][4], bfh[4][2], bfl[4][2];
#pragma unroll
            for (int mt = 0; mt < 4; mt++) {
                int r0 = wm * 64 + mt * 16;
                int i0 = (r0 + g) * 20 + kb2 + t;
                int i1 = (r0 + 8 + g) * 20 + kb2 + t;
                afh[mt][0] = Ah2[i0];     afl[mt][0] = Al2[i0];
                afh[mt][1] = Ah2[i1];     afl[mt][1] = Al2[i1];
                afh[mt][2] = Ah2[i0 + 4]; afl[mt][2] = Al2[i0 + 4];
                afh[mt][3] = Ah2[i1 + 4]; afl[mt][3] = Al2[i1 + 4];
            }
#pragma unroll
            for (int nt = 0; nt < 4; nt++) {
                int c0 = wn * 32 + nt * 8;
                int i0 = (kb2 + t) * 136 + c0 + g;
                int i1 = (kb2 + t + 4) * 136 + c0 + g;
                bfh[nt][0] = Bh2[i0]; bfl[nt][0] = Bl2[i0];
                bfh[nt][1] = Bh2[i1]; bfl[nt][1] = Bl2[i1];
            }
#pragma unroll
            for (int mt = 0; mt < 4; mt++)
#pragma unroll
                for (int nt = 0; nt < 4; nt++)
                    mma3_f16(acc[mt][nt], afh[mt], afl[mt], bfh[nt], bfl[nt]);
        }
        __syncthreads();                        // buffer (i&1) fully consumed
        if (i + 2 < nk) load_stage((i + 2) * 32, i & 1);
        CP_COMMIT();                            // (possibly empty group)
        CP_WAIT1();                             // stage i+1 complete
        __syncthreads();
    }

    // ---- epilogue ----
    if (mode == 0) {
#pragma unroll
        for (int mt = 0; mt < 4; mt++) {
            int row = bm + wm * 64 + mt * 16 + g;
#pragma unroll
            for (int nt = 0; nt < 4; nt++) {
                int col = bn + wn * 32 + nt * 8 + 2 * t;
                *reinterpret_cast<float2*>(Cf + (size_t)row * N + col) =
                    make_float2(acc[mt][nt][0], acc[mt][nt][1]);
                *reinterpret_cast<float2*>(Cf + (size_t)(row + 8) * N + col) =
                    make_float2(acc[mt][nt][2], acc[mt][nt][3]);
            }
        }
    } else {
#pragma unroll
        for (int mt = 0; mt < 4; mt++) {
            int row = bm + wm * 64 + mt * 16 + g;
#pragma unroll
            for (int nt = 0; nt < 4; nt++) {
                int col = bn + wn * 32 + nt * 8 + 2 * t;
                uint32_t hh, ll;
                f16_split2(acc[mt][nt][0], acc[mt][nt][1], hh, ll);
                *reinterpret_cast<uint32_t*>(Ch + (size_t)row * N + col) = hh;
                *reinterpret_cast<uint32_t*>(Cl + (size_t)row * N + col) = ll;
                f16_split2(acc[mt][nt][2], acc[mt][nt][3], hh, ll);
                *reinterpret_cast<uint32_t*>(Ch + (size_t)(row + 8) * N + col) = hh;
                *reinterpret_cast<uint32_t*>(Cl + (size_t)(row + 8) * N + col) = ll;
            }
        }
    }
}

// ---------------------------------------------------------------------------
// Flash attention, all inputs pre-split fp16 (unchanged from round 13).
// Block = 128 thr (4 warps), 64 q-rows. 55296 B smem, 3 CTAs/SM.
// NOTE: reference MULTIPLIES logits by sqrt(64)=8.
// ---------------------------------------------------------------------------
#define FKT (64 * 36)    // 2304
#define FVT (32 * 72)    // 2304
#define FLASH_SMEM ((2 * FKT + 2 * FVT + 2 * FKT) * 4)   // 55296 bytes

__global__ void __launch_bounds__(128, 3)
flash_f16p_kernel(const __half* __restrict__ Qh_g, const __half* __restrict__ Ql_g,
                  const __half* __restrict__ KVh_g, const __half* __restrict__ KVl_g,
                  __half* __restrict__ Oh, __half* __restrict__ Ol) {
    extern __shared__ uint32_t sm[];
    uint32_t* Kh2 = sm;                 // 2304
    uint32_t* Kl2 = sm + FKT;           // 2304
    uint32_t* Vh2 = sm + 2 * FKT;       // 2304
    uint32_t* Vl2 = Vh2 + FVT;          // 2304
    uint32_t* Prh = Vh2 + 2 * FVT;      // 2304  (V raw ∪ P operand; Q staged via Vh2/Vl2)
    uint32_t* Prl = Prh + FKT;          // 2304
    const uint32_t kh_s = smem_u32(Kh2);
    const uint32_t kl_s = smem_u32(Kl2);
    const uint32_t vh_s = smem_u32(Vh2);
    const uint32_t vl_s = smem_u32(Vl2);
    const uint32_t ph_s = smem_u32(Prh);
    const uint32_t pl_s = smem_u32(Prl);

    const int tid  = threadIdx.x;
    const int lane = tid & 31;
    const int warp = tid >> 5;
    const int g = lane >> 2;
    const int t = lane & 3;
    const int wr = warp * 16;

    const int b  = blockIdx.z;
    const int h  = blockIdx.y;
    const int q0 = blockIdx.x * 64;

    const __half* Kbh = KVh_g + (size_t)b * 2048 * 2048 + h * 64;
    const __half* Kbl = KVl_g + (size_t)b * 2048 * 2048 + h * 64;

    auto load_K = [&](int j0) {
#pragma unroll
        for (int p = 0; p < 4; p++) {
            int idx = tid + p * 128;          // 512 chunks per buffer
            int r  = idx >> 3;
            int cu = (idx & 7) << 2;
            cp16(kh_s + (uint32_t)(r * 36 + cu) * 4u, Kbh + (size_t)(j0 + r) * 2048 + cu * 2);
            cp16(kl_s + (uint32_t)(r * 36 + cu) * 4u, Kbl + (size_t)(j0 + r) * 2048 + cu * 2);
        }
    };
    auto load_V = [&](int j0) {
#pragma unroll
        for (int p = 0; p < 4; p++) {
            int idx = tid + p * 128;
            int r  = idx >> 3;
            int cu = (idx & 7) << 2;
            cp16(ph_s + (uint32_t)(r * 36 + cu) * 4u, Kbh + (size_t)(j0 + r) * 2048 + 1024 + cu * 2);
            cp16(pl_s + (uint32_t)(r * 36 + cu) * 4u, Kbl + (size_t)(j0 + r) * 2048 + 1024 + cu * 2);
        }
    };

    // ---- prologue: K0, V0, Q (staged via Vh2/Vl2) ----
    load_K(0); CP_COMMIT();
    load_V(0); CP_COMMIT();
    {
        const __half* Qbh = Qh_g + (size_t)(b * 2048 + q0) * 1024 + h * 64;
        const __half* Qbl = Ql_g + (size_t)(b * 2048 + q0) * 1024 + h * 64;
#pragma unroll
        for (int p = 0; p < 4; p++) {
            int idx = tid + p * 128;
            int r  = idx >> 3;
            int cu = (idx & 7) << 2;
            cp16(vh_s + (uint32_t)(r * 36 + cu) * 4u, Qbh + (size_t)r * 1024 + cu * 2);
            cp16(vl_s + (uint32_t)(r * 36 + cu) * 4u, Qbl + (size_t)r * 1024 + cu * 2);
        }
        CP_COMMIT();
    }
    CP_WAIT0();
    __syncthreads();

    uint32_t qh[4][4], ql[4][4];
#pragma unroll
    for (int ks = 0; ks < 4; ks++) {
        int kb = ks * 8;
        int i0 = (wr + g) * 36 + kb + t;
        int i1 = (wr + 8 + g) * 36 + kb + t;
        qh[ks][0] = Vh2[i0];     ql[ks][0] = Vl2[i0];
        qh[ks][1] = Vh2[i1];     ql[ks][1] = Vl2[i1];
        qh[ks][2] = Vh2[i0 + 4]; ql[ks][2] = Vl2[i0 + 4];
        qh[ks][3] = Vh2[i1 + 4]; ql[ks][3] = Vl2[i1 + 4];
    }
    __syncthreads();   // Vh2/Vl2 free for V repack

    float of[8][4];
#pragma unroll
    for (int i = 0; i < 8; i++)
#pragma unroll
        for (int v = 0; v < 4; v++) of[i][v] = 0.f;
    float m0 = -1e30f, m1 = -1e30f, l0 = 0.f, l1 = 0.f;

    for (int it = 0; it < 32; it++) {
        CP_WAIT0();          // K(it) and V(it) complete
        __syncthreads();

        // ---- repack V raw (pairs along d) -> Vh2/Vl2 (pairs along j) ----
#pragma unroll
        for (int p = 0; p < 8; p++) {
            int idx = tid + p * 128;         // 1024 (jp,dp) tasks
            int jp = idx >> 5;               // 0..31
            int dp = idx & 31;               // 0..31
            uint32_t X = Prh[(2 * jp) * 36 + dp];
            uint32_t Y = Prh[(2 * jp + 1) * 36 + dp];
            Vh2[jp * 72 + 2 * dp]     = __byte_perm(X, Y, 0x5410);
            Vh2[jp * 72 + 2 * dp + 1] = __byte_perm(X, Y, 0x7632);
            X = Prl[(2 * jp) * 36 + dp];
            Y = Prl[(2 * jp + 1) * 36 + dp];
            Vl2[jp * 72 + 2 * dp]     = __byte_perm(X, Y, 0x5410);
            Vl2[jp * 72 + 2 * dp + 1] = __byte_perm(X, Y, 0x7632);
        }
        __syncthreads();     // Vh2 ready; Pregion free

        // ---- S = Q K^T ----
        float sf[8][4];
#pragma unroll
        for (int nt = 0; nt < 8; nt++)
#pragma unroll
            for (int v = 0; v < 4; v++) sf[nt][v] = 0.f;
#pragma unroll
        for (int ks = 0; ks < 4; ks++) {
            int kb2 = ks * 8;
#pragma unroll
            for (int nt = 0; nt < 8; nt++) {
                int i0 = (nt * 8 + g) * 36 + kb2 + t;
                uint32_t bh[2] = { Kh2[i0], Kh2[i0 + 4] };
                uint32_t bl[2] = { Kl2[i0], Kl2[i0 + 4] };
                mma3_f16(sf[nt], qh[ks], ql[ks], bh, bl);
            }
        }
        __syncthreads();     // all warps done reading K
        if (it + 1 < 32) load_K((it + 1) * 64);   // prefetch next K
        CP_COMMIT();

        // ---- online softmax (x8 scale; rows g and g+8) ----
        float r0m = -1e30f, r1m = -1e30f;
#pragma unroll
        for (int nt = 0; nt < 8; nt++) {
            sf[nt][0] *= 8.f; sf[nt][1] *= 8.f; sf[nt][2] *= 8.f; sf[nt][3] *= 8.f;
            r0m = fmaxf(r0m, fmaxf(sf[nt][0], sf[nt][1]));
            r1m = fmaxf(r1m, fmaxf(sf[nt][2], sf[nt][3]));
        }
        r0m = fmaxf(r0m, __shfl_xor_sync(0xffffffffu, r0m, 1));
        r0m = fmaxf(r0m, __shfl_xor_sync(0xffffffffu, r0m, 2));
        r1m = fmaxf(r1m, __shfl_xor_sync(0xffffffffu, r1m, 1));
        r1m = fmaxf(r1m, __shfl_xor_sync(0xffffffffu, r1m, 2));

        float mn0 = fmaxf(m0, r0m), mn1 = fmaxf(m1, r1m);
        float cr0 = __expf(m0 - mn0), cr1 = __expf(m1 - mn1);
        float s0 = 0.f, s1 = 0.f;
#pragma unroll
        for (int nt = 0; nt < 8; nt++) {
            sf[nt][0] = __expf(sf[nt][0] - mn0);
            sf[nt][1] = __expf(sf[nt][1] - mn0);
            sf[nt][2] = __expf(sf[nt][2] - mn1);
            sf[nt][3] = __expf(sf[nt][3] - mn1);
            s0 += sf[nt][0] + sf[nt][1];
            s1 += sf[nt][2] + sf[nt][3];
        }
        s0 += __shfl_xor_sync(0xffffffffu, s0, 1);
        s0 += __shfl_xor_sync(0xffffffffu, s0, 2);
        s1 += __shfl_xor_sync(0xffffffffu, s1, 1);
        s1 += __shfl_xor_sync(0xffffffffu, s1, 2);
        l0 = l0 * cr0 + s0;  m0 = mn0;
        l1 = l1 * cr1 + s1;  m1 = mn1;
#pragma unroll
        for (int dt = 0; dt < 8; dt++) {
            of[dt][0] *= cr0; of[dt][1] *= cr0;
            of[dt][2] *= cr1; of[dt][3] *= cr1;
        }

        // ---- stage P fp16 hi/lo into Pregion (per-warp-private rows) ----
#pragma unroll
        for (int nt = 0; nt < 8; nt++) {
            uint32_t hh, ll;
            f16_split2(sf[nt][0], sf[nt][1], hh, ll);
            Prh[(wr + g) * 36 + nt * 4 + t] = hh;
            Prl[(wr + g) * 36 + nt * 4 + t] = ll;
            f16_split2(sf[nt][2], sf[nt][3], hh, ll);
            Prh[(wr + 8 + g) * 36 + nt * 4 + t] = hh;
            Prl[(wr + 8 + g) * 36 + nt * 4 + t] = ll;
        }
        __syncwarp();

        // ---- O += P V ----
#pragma unroll
        for (int ks = 0; ks < 4; ks++) {
            int kb2 = ks * 8;
            int i0 = (wr + g) * 36 + kb2 + t;
            int i1 = (wr + 8 + g) * 36 + kb2 + t;
            uint32_t ah[4] = { Prh[i0], Prh[i1], Prh[i0 + 4], Prh[i1 + 4] };
            uint32_t al[4] = { Prl[i0], Prl[i1], Prl[i0 + 4], Prl[i1 + 4] };
#pragma unroll
            for (int nt = 0; nt < 8; nt++) {
                int j0i = (kb2 + t) * 72 + nt * 8 + g;
                int j1i = (kb2 + t + 4) * 72 + nt * 8 + g;
                uint32_t bh[2] = { Vh2[j0i], Vh2[j1i] };
                uint32_t bl[2] = { Vl2[j0i], Vl2[j1i] };
                mma3_f16(of[nt], ah, al, bh, bl);
            }
        }
        __syncthreads();     // all warps done with Pregion + Vh2
        if (it + 1 < 32) load_V((it + 1) * 64);   // prefetch next V into Pregion
        CP_COMMIT();
    }

    // ---- epilogue: split-fp16 ao ----
    float inv0 = 1.f / l0, inv1 = 1.f / l1;
    int row0 = b * 2048 + q0 + wr + g;
#pragma unroll
    for (int nt = 0; nt < 8; nt++) {
        int col = h * 64 + nt * 8 + 2 * t;
        uint32_t hh, ll;
        f16_split2(of[nt][0] * inv0, of[nt][1] * inv0, hh, ll);
        *reinterpret_cast<uint32_t*>(Oh + (size_t)row0 * 1024 + col) = hh;
        *reinterpret_cast<uint32_t*>(Ol + (size_t)row0 * 1024 + col) = ll;
        f16_split2(of[nt][2] * inv1, of[nt][3] * inv1, hh, ll);
        *reinterpret_cast<uint32_t*>(Oh + (size_t)(row0 + 8) * 1024 + col) = hh;
        *reinterpret_cast<uint32_t*>(Ol + (size_t)(row0 + 8) * 1024 + col) = ll;
    }
}

// ---------------------------------------------------------------------------
extern "C" void kernel_launch(void* const* d_in, const int* in_sizes, int n_in,
                              void* d_out, int out_size) {
    const float* x     = (const float*)d_in[0];   // [2,2048,1024]
    const float* w_q   = (const float*)d_in[1];   // [1024,1024]
    const float* w_vk  = (const float*)d_in[2];   // [1024,2048]
    const float* w_out = (const float*)d_in[3];   // [1024,1024]
    float* out = (float*)d_out;                   // [2,2048,1024]

    __half *xh, *xl, *qh, *ql, *kvh, *kvl, *aoh, *aol;
    uint32_t *wqh, *wql, *wvkh, *wvkl, *woh, *wol;
    cudaGetSymbolAddress((void**)&xh,  g_xh);   cudaGetSymbolAddress((void**)&xl,  g_xl);
    cudaGetSymbolAddress((void**)&wqh, g_wq_h); cudaGetSymbolAddress((void**)&wql, g_wq_l);
    cudaGetSymbolAddress((void**)&wvkh, g_wvk_h); cudaGetSymbolAddress((void**)&wvkl, g_wvk_l);
    cudaGetSymbolAddress((void**)&woh, g_wo_h); cudaGetSymbolAddress((void**)&wol, g_wo_l);
    cudaGetSymbolAddress((void**)&qh,  g_qh);   cudaGetSymbolAddress((void**)&ql,  g_ql);
    cudaGetSymbolAddress((void**)&kvh, g_kvh);  cudaGetSymbolAddress((void**)&kvl, g_kvl);
    cudaGetSymbolAddress((void**)&aoh, g_aoh);  cudaGetSymbolAddress((void**)&aol, g_aol);

    cudaFuncSetAttribute(gemm_f16p_kernel,
                         cudaFuncAttributeMaxDynamicSharedMemorySize, GEMM_SMEM);
    cudaFuncSetAttribute(flash_f16p_kernel,
                         cudaFuncAttributeMaxDynamicSharedMemorySize, FLASH_SMEM);

    // presplit (once per launch; cheap)
    presplit_plain<<<4096, 256>>>(x, xh, xl, 4096 * 1024);
    presplit_wpair<<<512,  256>>>(w_q,   wqh,  wql,  1024, 1024);
    presplit_wpair<<<1024, 256>>>(w_vk,  wvkh, wvkl, 1024, 2048);
    presplit_wpair<<<512,  256>>>(w_out, woh,  wol,  1024, 1024);

    // Q = x @ w_q  -> split fp16
    gemm_f16p_kernel<<<dim3(8, 32), 256, GEMM_SMEM>>>(xh, xl, wqh, wql,
                                           nullptr, qh, ql, 4096, 1024, 1024, 1);
    // KV = x @ w_vk -> split fp16
    gemm_f16p_kernel<<<dim3(16, 32), 256, GEMM_SMEM>>>(xh, xl, wvkh, wvkl,
                                            nullptr, kvh, kvl, 4096, 2048, 1024, 1);
    // attention -> split fp16 ao
    flash_f16p_kernel<<<dim3(32, 16, 2), 128, FLASH_SMEM>>>(qh, ql, kvh, kvl, aoh, aol);
    // out = ao @ w_out -> fp32
    gemm_f16p_kernel<<<dim3(8, 32), 256, GEMM_SMEM>>>(aoh, aol, woh, wol,
                                           out, nullptr, nullptr, 4096, 1024, 1024, 0);
}

// round 16
// speedup vs baseline: 1.0294x; 1.0294x over previous
#include <cuda_runtime.h>
#include <cuda_fp16.h>
#include <cstdint>

// ---------------------------------------------------------------------------
// Split-fp16 global tensors (static device memory — no cudaMalloc anywhere)
// ---------------------------------------------------------------------------
__device__ __half g_xh [4096u * 1024u];
__device__ __half g_xl [4096u * 1024u];
__device__ uint32_t g_wq_h [512u * 1024u];   // pre-paired across k: u32 = {w[2k],w[2k+1]}
__device__ uint32_t g_wq_l [512u * 1024u];
__device__ uint32_t g_wvk_h[512u * 2048u];
__device__ uint32_t g_wvk_l[512u * 2048u];
__device__ uint32_t g_wo_h [512u * 1024u];
__device__ uint32_t g_wo_l [512u * 1024u];
__device__ __half g_qh [4096u * 1024u];
__device__ __half g_ql [4096u * 1024u];
__device__ __half g_kvh[4096u * 2048u];
__device__ __half g_kvl[4096u * 2048u];
__device__ __half g_aoh[4096u * 1024u];      // ao stored hi-only (2-term out path)

// ---------------------------------------------------------------------------
// helpers
// ---------------------------------------------------------------------------
// Markidis split of (x0,x1) into packed half2 hi/lo; x0 in LOW half.
__device__ __forceinline__ void f16_split2(float x0, float x1, uint32_t& hi, uint32_t& lo) {
    __half2 h = __floats2half2_rn(x0, x1);
    __half2 l = __floats2half2_rn(x0 - __low2float(h), x1 - __high2float(h));
    hi = *reinterpret_cast<uint32_t*>(&h);
    lo = *reinterpret_cast<uint32_t*>(&l);
}
__device__ __forceinline__ uint32_t f16_pack2(float x0, float x1) {
    __half2 h = __floats2half2_rn(x0, x1);
    return *reinterpret_cast<uint32_t*>(&h);
}
// fp16 m16n8k16 (validated layouts)
__device__ __forceinline__ void mma_f16(float c[4], const uint32_t a[4], const uint32_t b[2]) {
    asm volatile(
        "mma.sync.aligned.m16n8k16.row.col.f32.f16.f16.f32 "
        "{%0,%1,%2,%3}, {%4,%5,%6,%7}, {%8,%9}, {%0,%1,%2,%3};\n"
        : "+f"(c[0]), "+f"(c[1]), "+f"(c[2]), "+f"(c[3])
        : "r"(a[0]), "r"(a[1]), "r"(a[2]), "r"(a[3]), "r"(b[0]), "r"(b[1]));
}
__device__ __forceinline__ void mma3_f16(float c[4], const uint32_t ah[4], const uint32_t al[4],
                                         const uint32_t bh[2], const uint32_t bl[2]) {
    mma_f16(c, ah, bl);
    mma_f16(c, al, bh);
    mma_f16(c, ah, bh);
}
__device__ __forceinline__ uint32_t smem_u32(const void* p) {
    return (uint32_t)__cvta_generic_to_shared(p);
}
__device__ __forceinline__ void cp16(uint32_t saddr, const void* gptr) {
    asm volatile("cp.async.cg.shared.global [%0], [%1], 16;\n" :: "r"(saddr), "l"(gptr));
}
#define CP_COMMIT() asm volatile("cp.async.commit_group;\n" ::: "memory")
#define CP_WAIT0()  asm volatile("cp.async.wait_group 0;\n" ::: "memory")

// ---------------------------------------------------------------------------
// presplit kernels (run once; pure bandwidth)
// ---------------------------------------------------------------------------
__global__ void presplit_plain(const float* __restrict__ x, __half* __restrict__ xh,
                               __half* __restrict__ xl, int n) {
    int i = (blockIdx.x * blockDim.x + threadIdx.x) * 4;
    if (i >= n) return;
    float4 v = *reinterpret_cast<const float4*>(x + i);
    uint32_t h0, l0, h1, l1;
    f16_split2(v.x, v.y, h0, l0);
    f16_split2(v.z, v.w, h1, l1);
    *reinterpret_cast<uint2*>(xh + i) = make_uint2(h0, h1);
    *reinterpret_cast<uint2*>(xl + i) = make_uint2(l0, l1);
}

// w [K][N] f32 -> u32 [K/2][N] pairs across k (low half = lower k)
__global__ void presplit_wpair(const float* __restrict__ w, uint32_t* __restrict__ wh,
                               uint32_t* __restrict__ wl, int K, int N) {
    int idx = blockIdx.x * blockDim.x + threadIdx.x;   // over (K/2)*(N/4)
    int kp = idx / (N >> 2);
    int n4 = (idx % (N >> 2)) * 4;
    if (kp >= (K >> 1)) return;
    const float* r0 = w + (size_t)(2 * kp) * N + n4;
    float4 a = *reinterpret_cast<const float4*>(r0);
    float4 b = *reinterpret_cast<const float4*>(r0 + N);
    uint32_t h[4], l[4];
    f16_split2(a.x, b.x, h[0], l[0]);
    f16_split2(a.y, b.y, h[1], l[1]);
    f16_split2(a.z, b.z, h[2], l[2]);
    f16_split2(a.w, b.w, h[3], l[3]);
    *reinterpret_cast<uint4*>(wh + (size_t)kp * N + n4) = make_uint4(h[0], h[1], h[2], h[3]);
    *reinterpret_cast<uint4*>(wl + (size_t)kp * N + n4) = make_uint4(l[0], l[1], l[2], l[3]);
}

// ---------------------------------------------------------------------------
// split-fp16 GEMM (round-13 proven structure), with 3-term / 2-term switch.
// C[M,N] = A[M,K] @ B[K,N]. A: row-major half hi/lo. B: pre-paired u32 [K/2][N].
// Block 128x128, BK=32, 256 thr (8 warps 2m x 4n), warp tile 64x32.
// mode 0: C fp32;  mode 1: C split-fp16 (Ch/Cl).
// terms 3: (Ah+Al)(Bh+Bl) - AlBl;  terms 2: Ah(Bh+Bl)  [Al_g unused]
// ---------------------------------------------------------------------------
#define GAH (128 * 20)
#define GBH (16 * 136)

__global__ void __launch_bounds__(256, 2)
gemm_f16p_kernel(const __half* __restrict__ Ah_g, const __half* __restrict__ Al_g,
                 const uint32_t* __restrict__ Bh_g, const uint32_t* __restrict__ Bl_g,
                 float* __restrict__ Cf, __half* __restrict__ Ch, __half* __restrict__ Cl,
                 int M, int N, int K, int mode, int terms) {
    __shared__ uint32_t Ah2[GAH], Al2[GAH], Bh2[GBH], Bl2[GBH];
    const uint32_t ah_s = smem_u32(Ah2);
    const uint32_t al_s = smem_u32(Al2);
    const uint32_t bh_s = smem_u32(Bh2);
    const uint32_t bl_s = smem_u32(Bl2);

    const int tid  = threadIdx.x;
    const int lane = tid & 31;
    const int warp = tid >> 5;
    const int g = lane >> 2;
    const int t = lane & 3;
    const int wm = warp >> 2;
    const int wn = warp & 3;
    const int bm = blockIdx.y * 128;
    const int bn = blockIdx.x * 128;
    const bool three = (terms == 3);

    float acc[4][4][4];
#pragma unroll
    for (int i = 0; i < 4; i++)
#pragma unroll
        for (int j = 0; j < 4; j++)
#pragma unroll
            for (int v = 0; v < 4; v++) acc[i][j][v] = 0.f;

    for (int k0 = 0; k0 < K; k0 += 32) {
        // ---- issue cp.async staging (fp16, no conversion) ----
#pragma unroll
        for (int p = 0; p < 2; p++) {
            int idx = tid + p * 256;           // 512 chunks per A buffer
            int r  = idx >> 2;
            int cu = (idx & 3) << 2;           // u32 offset in row (0,4,8,12)
            cp16(ah_s + (uint32_t)(r * 20 + cu) * 4u,
                 Ah_g + (size_t)(bm + r) * K + k0 + cu * 2);
            if (three)
                cp16(al_s + (uint32_t)(r * 20 + cu) * 4u,
                     Al_g + (size_t)(bm + r) * K + k0 + cu * 2);
        }
#pragma unroll
        for (int p = 0; p < 2; p++) {
            int idx = tid + p * 256;           // 512 chunks per B buffer
            int kp = idx >> 5;
            int cu = (idx & 31) << 2;
            cp16(bh_s + (uint32_t)(kp * 136 + cu) * 4u,
                 Bh_g + (size_t)((k0 >> 1) + kp) * N + bn + cu);
            cp16(bl_s + (uint32_t)(kp * 136 + cu) * 4u,
                 Bl_g + (size_t)((k0 >> 1) + kp) * N + bn + cu);
        }
        CP_COMMIT();
        CP_WAIT0();
        __syncthreads();

        // ---- MMA phase (validated indexing) ----
#pragma unroll
        for (int ks = 0; ks < 2; ks++) {
            const int kb2 = ks * 8;
            uint32_t afh[4][4], afl[4][4], bfh[4][2], bfl[4][2];
#pragma unroll
            for (int mt = 0; mt < 4; mt++) {
                int r0 = wm * 64 + mt * 16;
                int i0 = (r0 + g) * 20 + kb2 + t;
                int i1 = (r0 + 8 + g) * 20 + kb2 + t;
                afh[mt][0] = Ah2[i0];
                afh[mt][1] = Ah2[i1];
                afh[mt][2] = Ah2[i0 + 4];
                afh[mt][3] = Ah2[i1 + 4];
                if (three) {
                    afl[mt][0] = Al2[i0];
                    afl[mt][1] = Al2[i1];
                    afl[mt][2] = Al2[i0 + 4];
                    afl[mt][3] = Al2[i1 + 4];
                }
            }
#pragma unroll
            for (int nt = 0; nt < 4; nt++) {
                int c0 = wn * 32 + nt * 8;
                int i0 = (kb2 + t) * 136 + c0 + g;
                int i1 = (kb2 + t + 4) * 136 + c0 + g;
                bfh[nt][0] = Bh2[i0]; bfl[nt][0] = Bl2[i0];
                bfh[nt][1] = Bh2[i1]; bfl[nt][1] = Bl2[i1];
            }
            if (three) {
#pragma unroll
                for (int mt = 0; mt < 4; mt++)
#pragma unroll
                    for (int nt = 0; nt < 4; nt++)
                        mma3_f16(acc[mt][nt], afh[mt], afl[mt], bfh[nt], bfl[nt]);
            } else {
#pragma unroll
                for (int mt = 0; mt < 4; mt++)
#pragma unroll
                    for (int nt = 0; nt < 4; nt++) {
                        mma_f16(acc[mt][nt], afh[mt], bfl[nt]);
                        mma_f16(acc[mt][nt], afh[mt], bfh[nt]);
                    }
            }
        }
        __syncthreads();   // buffers consumed; next iter may overwrite
    }

    // ---- epilogue ----
    if (mode == 0) {
#pragma unroll
        for (int mt = 0; mt < 4; mt++) {
            int row = bm + wm * 64 + mt * 16 + g;
#pragma unroll
            for (int nt = 0; nt < 4; nt++) {
                int col = bn + wn * 32 + nt * 8 + 2 * t;
                *reinterpret_cast<float2*>(Cf + (size_t)row * N + col) =
                    make_float2(acc[mt][nt][0], acc[mt][nt][1]);
                *reinterpret_cast<float2*>(Cf + (size_t)(row + 8) * N + col) =
                    make_float2(acc[mt][nt][2], acc[mt][nt][3]);
            }
        }
    } else {
#pragma unroll
        for (int mt = 0; mt < 4; mt++) {
            int row = bm + wm * 64 + mt * 16 + g;
#pragma unroll
            for (int nt = 0; nt < 4; nt++) {
                int col = bn + wn * 32 + nt * 8 + 2 * t;
                uint32_t hh, ll;
                f16_split2(acc[mt][nt][0], acc[mt][nt][1], hh, ll);
                *reinterpret_cast<uint32_t*>(Ch + (size_t)row * N + col) = hh;
                *reinterpret_cast<uint32_t*>(Cl + (size_t)row * N + col) = ll;
                f16_split2(acc[mt][nt][2], acc[mt][nt][3], hh, ll);
                *reinterpret_cast<uint32_t*>(Ch + (size_t)(row + 8) * N + col) = hh;
                *reinterpret_cast<uint32_t*>(Cl + (size_t)(row + 8) * N + col) = ll;
            }
        }
    }
}

// ---------------------------------------------------------------------------
// Flash attention (round-13 structure). QK^T = 3-term; PV = 2-term (P hi-only):
//   O += Ph*Vh + Ph*Vl.  Output ao stored hi-only.
// smem (u32): Kh2/Kl2 [64][36], Vh2/Vl2 [32][72], Pregion [64][36] x2
//   (V raw staging hi/lo; P operand uses hi region only).
// NOTE: reference MULTIPLIES logits by sqrt(64)=8.
// ---------------------------------------------------------------------------
#define FKT (64 * 36)
#define FVT (32 * 72)
#define FLASH_SMEM ((2 * FKT + 2 * FVT + 2 * FKT) * 4)   // 55296 bytes

__global__ void __launch_bounds__(128, 3)
flash_f16p_kernel(const __half* __restrict__ Qh_g, const __half* __restrict__ Ql_g,
                  const __half* __restrict__ KVh_g, const __half* __restrict__ KVl_g,
                  __half* __restrict__ Oh) {
    extern __shared__ uint32_t sm[];
    uint32_t* Kh2 = sm;
    uint32_t* Kl2 = sm + FKT;
    uint32_t* Vh2 = sm + 2 * FKT;
    uint32_t* Vl2 = Vh2 + FVT;
    uint32_t* Prh = Vh2 + 2 * FVT;      // V raw hi ∪ P operand
    uint32_t* Prl = Prh + FKT;          // V raw lo
    const uint32_t kh_s = smem_u32(Kh2);
    const uint32_t kl_s = smem_u32(Kl2);
    const uint32_t vh_s = smem_u32(Vh2);
    const uint32_t vl_s = smem_u32(Vl2);
    const uint32_t ph_s = smem_u32(Prh);
    const uint32_t pl_s = smem_u32(Prl);

    const int tid  = threadIdx.x;
    const int lane = tid & 31;
    const int warp = tid >> 5;
    const int g = lane >> 2;
    const int t = lane & 3;
    const int wr = warp * 16;

    const int b  = blockIdx.z;
    const int h  = blockIdx.y;
    const int q0 = blockIdx.x * 64;

    const __half* Kbh = KVh_g + (size_t)b * 2048 * 2048 + h * 64;
    const __half* Kbl = KVl_g + (size_t)b * 2048 * 2048 + h * 64;

    auto load_K = [&](int j0) {
#pragma unroll
        for (int p = 0; p < 4; p++) {
            int idx = tid + p * 128;
            int r  = idx >> 3;
            int cu = (idx & 7) << 2;
            cp16(kh_s + (uint32_t)(r * 36 + cu) * 4u, Kbh + (size_t)(j0 + r) * 2048 + cu * 2);
            cp16(kl_s + (uint32_t)(r * 36 + cu) * 4u, Kbl + (size_t)(j0 + r) * 2048 + cu * 2);
        }
    };
    auto load_V = [&](int j0) {
#pragma unroll
        for (int p = 0; p < 4; p++) {
            int idx = tid + p * 128;
            int r  = idx >> 3;
            int cu = (idx & 7) << 2;
            cp16(ph_s + (uint32_t)(r * 36 + cu) * 4u, Kbh + (size_t)(j0 + r) * 2048 + 1024 + cu * 2);
            cp16(pl_s + (uint32_t)(r * 36 + cu) * 4u, Kbl + (size_t)(j0 + r) * 2048 + 1024 + cu * 2);
        }
    };

    // ---- prologue: K0, V0, Q (staged via Vh2/Vl2) ----
    load_K(0); CP_COMMIT();
    load_V(0); CP_COMMIT();
    {
        const __half* Qbh = Qh_g + (size_t)(b * 2048 + q0) * 1024 + h * 64;
        const __half* Qbl = Ql_g + (size_t)(b * 2048 + q0) * 1024 + h * 64;
#pragma unroll
        for (int p = 0; p < 4; p++) {
            int idx = tid + p * 128;
            int r  = idx >> 3;
            int cu = (idx & 7) << 2;
            cp16(vh_s + (uint32_t)(r * 36 + cu) * 4u, Qbh + (size_t)r * 1024 + cu * 2);
            cp16(vl_s + (uint32_t)(r * 36 + cu) * 4u, Qbl + (size_t)r * 1024 + cu * 2);
        }
        CP_COMMIT();
    }
    CP_WAIT0();
    __syncthreads();

    uint32_t qh[4][4], ql[4][4];
#pragma unroll
    for (int ks = 0; ks < 4; ks++) {
        int kb = ks * 8;
        int i0 = (wr + g) * 36 + kb + t;
        int i1 = (wr + 8 + g) * 36 + kb + t;
        qh[ks][0] = Vh2[i0];     ql[ks][0] = Vl2[i0];
        qh[ks][1] = Vh2[i1];     ql[ks][1] = Vl2[i1];
        qh[ks][2] = Vh2[i0 + 4]; ql[ks][2] = Vl2[i0 + 4];
        qh[ks][3] = Vh2[i1 + 4]; ql[ks][3] = Vl2[i1 + 4];
    }
    __syncthreads();   // Vh2/Vl2 free for V repack

    float of[8][4];
#pragma unroll
    for (int i = 0; i < 8; i++)
#pragma unroll
        for (int v = 0; v < 4; v++) of[i][v] = 0.f;
    float m0 = -1e30f, m1 = -1e30f, l0 = 0.f, l1 = 0.f;

    for (int it = 0; it < 32; it++) {
        CP_WAIT0();          // K(it) and V(it) complete
        __syncthreads();

        // ---- repack V raw (pairs along d) -> Vh2/Vl2 (pairs along j) ----
#pragma unroll
        for (int p = 0; p < 8; p++) {
            int idx = tid + p * 128;         // 1024 (jp,dp) tasks
            int jp = idx >> 5;               // 0..31
            int dp = idx & 31;               // 0..31
            uint32_t X = Prh[(2 * jp) * 36 + dp];
            uint32_t Y = Prh[(2 * jp + 1) * 36 + dp];
            Vh2[jp * 72 + 2 * dp]     = __byte_perm(X, Y, 0x5410);
            Vh2[jp * 72 + 2 * dp + 1] = __byte_perm(X, Y, 0x7632);
            X = Prl[(2 * jp) * 36 + dp];
            Y = Prl[(2 * jp + 1) * 36 + dp];
            Vl2[jp * 72 + 2 * dp]     = __byte_perm(X, Y, 0x5410);
            Vl2[jp * 72 + 2 * dp + 1] = __byte_perm(X, Y, 0x7632);
        }
        __syncthreads();     // Vh2 ready; Pregion free

        // ---- S = Q K^T (3-term) ----
        float sf[8][4];
#pragma unroll
        for (int nt = 0; nt < 8; nt++)
#pragma unroll
            for (int v = 0; v < 4; v++) sf[nt][v] = 0.f;
#pragma unroll
        for (int ks = 0; ks < 4; ks++) {
            int kb2 = ks * 8;
#pragma unroll
            for (int nt = 0; nt < 8; nt++) {
                int i0 = (nt * 8 + g) * 36 + kb2 + t;
                uint32_t bh[2] = { Kh2[i0], Kh2[i0 + 4] };
                uint32_t bl[2] = { Kl2[i0], Kl2[i0 + 4] };
                mma3_f16(sf[nt], qh[ks], ql[ks], bh, bl);
            }
        }
        __syncthreads();     // all warps done reading K
        if (it + 1 < 32) load_K((it + 1) * 64);   // prefetch next K
        CP_COMMIT();

        // ---- online softmax (x8 scale; rows g and g+8) ----
        float r0m = -1e30f, r1m = -1e30f;
#pragma unroll
        for (int nt = 0; nt < 8; nt++) {
            sf[nt][0] *= 8.f; sf[nt][1] *= 8.f; sf[nt][2] *= 8.f; sf[nt][3] *= 8.f;
            r0m = fmaxf(r0m, fmaxf(sf[nt][0], sf[nt][1]));
            r1m = fmaxf(r1m, fmaxf(sf[nt][2], sf[nt][3]));
        }
        r0m = fmaxf(r0m, __shfl_xor_sync(0xffffffffu, r0m, 1));
        r0m = fmaxf(r0m, __shfl_xor_sync(0xffffffffu, r0m, 2));
        r1m = fmaxf(r1m, __shfl_xor_sync(0xffffffffu, r1m, 1));
        r1m = fmaxf(r1m, __shfl_xor_sync(0xffffffffu, r1m, 2));

        float mn0 = fmaxf(m0, r0m), mn1 = fmaxf(m1, r1m);
        float cr0 = __expf(m0 - mn0), cr1 = __expf(m1 - mn1);
        float s0 = 0.f, s1 = 0.f;
#pragma unroll
        for (int nt = 0; nt < 8; nt++) {
            sf[nt][0] = __expf(sf[nt][0] - mn0);
            sf[nt][1] = __expf(sf[nt][1] - mn0);
            sf[nt][2] = __expf(sf[nt][2] - mn1);
            sf[nt][3] = __expf(sf[nt][3] - mn1);
            s0 += sf[nt][0] + sf[nt][1];
            s1 += sf[nt][2] + sf[nt][3];
        }
        s0 += __shfl_xor_sync(0xffffffffu, s0, 1);
        s0 += __shfl_xor_sync(0xffffffffu, s0, 2);
        s1 += __shfl_xor_sync(0xffffffffu, s1, 1);
        s1 += __shfl_xor_sync(0xffffffffu, s1, 2);
        l0 = l0 * cr0 + s0;  m0 = mn0;
        l1 = l1 * cr1 + s1;  m1 = mn1;
#pragma unroll
        for (int dt = 0; dt < 8; dt++) {
            of[dt][0] *= cr0; of[dt][1] *= cr0;
            of[dt][2] *= cr1; of[dt][3] *= cr1;
        }

        // ---- stage P fp16 HI-ONLY into Prh (per-warp-private rows) ----
#pragma unroll
        for (int nt = 0; nt < 8; nt++) {
            Prh[(wr + g) * 36 + nt * 4 + t]     = f16_pack2(sf[nt][0], sf[nt][1]);
            Prh[(wr + 8 + g) * 36 + nt * 4 + t] = f16_pack2(sf[nt][2], sf[nt][3]);
        }
        __syncwarp();

        // ---- O += P V (2-term: Ph*Vh + Ph*Vl) ----
#pragma unroll
        for (int ks = 0; ks < 4; ks++) {
            int kb2 = ks * 8;
            int i0 = (wr + g) * 36 + kb2 + t;
            int i1 = (wr + 8 + g) * 36 + kb2 + t;
            uint32_t ah[4] = { Prh[i0], Prh[i1], Prh[i0 + 4], Prh[i1 + 4] };
#pragma unroll
            for (int nt = 0; nt < 8; nt++) {
                int j0i = (kb2 + t) * 72 + nt * 8 + g;
                int j1i = (kb2 + t + 4) * 72 + nt * 8 + g;
                uint32_t bh[2] = { Vh2[j0i], Vh2[j1i] };
                uint32_t bl[2] = { Vl2[j0i], Vl2[j1i] };
                mma_f16(of[nt], ah, bl);
                mma_f16(of[nt], ah, bh);
            }
        }
        __syncthreads();     // all warps done with Pregion + Vh2
        if (it + 1 < 32) load_V((it + 1) * 64);   // prefetch next V into Pregion
        CP_COMMIT();
    }

    // ---- epilogue: ao hi-only fp16 ----
    float inv0 = 1.f / l0, inv1 = 1.f / l1;
    int row0 = b * 2048 + q0 + wr + g;
#pragma unroll
    for (int nt = 0; nt < 8; nt++) {
        int col = h * 64 + nt * 8 + 2 * t;
        *reinterpret_cast<uint32_t*>(Oh + (size_t)row0 * 1024 + col) =
            f16_pack2(of[nt][0] * inv0, of[nt][1] * inv0);
        *reinterpret_cast<uint32_t*>(Oh + (size_t)(row0 + 8) * 1024 + col) =
            f16_pack2(of[nt][2] * inv1, of[nt][3] * inv1);
    }
}

// ---------------------------------------------------------------------------
extern "C" void kernel_launch(void* const* d_in, const int* in_sizes, int n_in,
                              void* d_out, int out_size) {
    const float* x     = (const float*)d_in[0];   // [2,2048,1024]
    const float* w_q   = (const float*)d_in[1];   // [1024,1024]
    const float* w_vk  = (const float*)d_in[2];   // [1024,2048]
    const float* w_out = (const float*)d_in[3];   // [1024,1024]
    float* out = (float*)d_out;                   // [2,2048,1024]

    __half *xh, *xl, *qh, *ql, *kvh, *kvl, *aoh;
    uint32_t *wqh, *wql, *wvkh, *wvkl, *woh, *wol;
    cudaGetSymbolAddress((void**)&xh,  g_xh);   cudaGetSymbolAddress((void**)&xl,  g_xl);
    cudaGetSymbolAddress((void**)&wqh, g_wq_h); cudaGetSymbolAddress((void**)&wql, g_wq_l);
    cudaGetSymbolAddress((void**)&wvkh, g_wvk_h); cudaGetSymbolAddress((void**)&wvkl, g_wvk_l);
    cudaGetSymbolAddress((void**)&woh, g_wo_h); cudaGetSymbolAddress((void**)&wol, g_wo_l);
    cudaGetSymbolAddress((void**)&qh,  g_qh);   cudaGetSymbolAddress((void**)&ql,  g_ql);
    cudaGetSymbolAddress((void**)&kvh, g_kvh);  cudaGetSymbolAddress((void**)&kvl, g_kvl);
    cudaGetSymbolAddress((void**)&aoh, g_aoh);

    cudaFuncSetAttribute(flash_f16p_kernel,
                         cudaFuncAttributeMaxDynamicSharedMemorySize, FLASH_SMEM);

    // presplit (once per launch; cheap)
    presplit_plain<<<4096, 256>>>(x, xh, xl, 4096 * 1024);
    presplit_wpair<<<512,  256>>>(w_q,   wqh,  wql,  1024, 1024);
    presplit_wpair<<<1024, 256>>>(w_vk,  wvkh, wvkl, 1024, 2048);
    presplit_wpair<<<512,  256>>>(w_out, woh,  wol,  1024, 1024);

    // Q = x @ w_q  -> split fp16 (3-term)
    gemm_f16p_kernel<<<dim3(8, 32), 256>>>(xh, xl, wqh, wql,
                                           nullptr, qh, ql, 4096, 1024, 1024, 1, 3);
    // KV = x @ w_vk -> split fp16 (3-term)
    gemm_f16p_kernel<<<dim3(16, 32), 256>>>(xh, xl, wvkh, wvkl,
                                            nullptr, kvh, kvl, 4096, 2048, 1024, 1, 3);
    // attention -> hi-only fp16 ao (QK 3-term, PV 2-term)
    flash_f16p_kernel<<<dim3(32, 16, 2), 128, FLASH_SMEM>>>(qh, ql, kvh, kvl, aoh);
    // out = ao @ w_out -> fp32 (2-term: aoh * (Wh + Wl))
    gemm_f16p_kernel<<<dim3(8, 32), 256>>>(aoh, nullptr, woh, wol,
                                           out, nullptr, nullptr, 4096, 1024, 1024, 0, 2);
}

// round 17
// speedup vs baseline: 1.1329x; 1.1005x over previous
#include <cuda_runtime.h>
#include <cuda_fp16.h>
#include <cstdint>

// ---------------------------------------------------------------------------
// Split-fp16 global tensors (static device memory — no cudaMalloc anywhere)
// ---------------------------------------------------------------------------
__device__ __half g_xh [4096u * 1024u];
__device__ __half g_xl [4096u * 1024u];
__device__ uint32_t g_wq_h [512u * 1024u];   // pre-paired across k: u32 = {w[2k],w[2k+1]}
__device__ uint32_t g_wq_l [512u * 1024u];
__device__ uint32_t g_wvk_h[512u * 2048u];
__device__ uint32_t g_wvk_l[512u * 2048u];
__device__ uint32_t g_wo_h [512u * 1024u];
__device__ uint32_t g_wo_l [512u * 1024u];
__device__ __half g_qh [4096u * 1024u];
__device__ __half g_ql [4096u * 1024u];
__device__ __half g_kvh[4096u * 2048u];
__device__ __half g_kvl[4096u * 2048u];      // lo used only for K half (cols<1024)
__device__ __half g_aoh[4096u * 1024u];      // ao stored hi-only (2-term out path)

// ---------------------------------------------------------------------------
// helpers
// ---------------------------------------------------------------------------
__device__ __forceinline__ void f16_split2(float x0, float x1, uint32_t& hi, uint32_t& lo) {
    __half2 h = __floats2half2_rn(x0, x1);
    __half2 l = __floats2half2_rn(x0 - __low2float(h), x1 - __high2float(h));
    hi = *reinterpret_cast<uint32_t*>(&h);
    lo = *reinterpret_cast<uint32_t*>(&l);
}
__device__ __forceinline__ uint32_t f16_pack2(float x0, float x1) {
    __half2 h = __floats2half2_rn(x0, x1);
    return *reinterpret_cast<uint32_t*>(&h);
}
// fp16 m16n8k16 (validated layouts)
__device__ __forceinline__ void mma_f16(float c[4], const uint32_t a[4], const uint32_t b[2]) {
    asm volatile(
        "mma.sync.aligned.m16n8k16.row.col.f32.f16.f16.f32 "
        "{%0,%1,%2,%3}, {%4,%5,%6,%7}, {%8,%9}, {%0,%1,%2,%3};\n"
        : "+f"(c[0]), "+f"(c[1]), "+f"(c[2]), "+f"(c[3])
        : "r"(a[0]), "r"(a[1]), "r"(a[2]), "r"(a[3]), "r"(b[0]), "r"(b[1]));
}
__device__ __forceinline__ void mma3_f16(float c[4], const uint32_t ah[4], const uint32_t al[4],
                                         const uint32_t bh[2], const uint32_t bl[2]) {
    mma_f16(c, ah, bl);
    mma_f16(c, al, bh);
    mma_f16(c, ah, bh);
}
__device__ __forceinline__ uint32_t smem_u32(const void* p) {
    return (uint32_t)__cvta_generic_to_shared(p);
}
__device__ __forceinline__ void cp16(uint32_t saddr, const void* gptr) {
    asm volatile("cp.async.cg.shared.global [%0], [%1], 16;\n" :: "r"(saddr), "l"(gptr));
}
#define CP_COMMIT() asm volatile("cp.async.commit_group;\n" ::: "memory")
#define CP_WAIT0()  asm volatile("cp.async.wait_group 0;\n" ::: "memory")

// ---------------------------------------------------------------------------
// presplit kernels (run once; pure bandwidth)
// ---------------------------------------------------------------------------
__global__ void presplit_plain(const float* __restrict__ x, __half* __restrict__ xh,
                               __half* __restrict__ xl, int n) {
    int i = (blockIdx.x * blockDim.x + threadIdx.x) * 4;
    if (i >= n) return;
    float4 v = *reinterpret_cast<const float4*>(x + i);
    uint32_t h0, l0, h1, l1;
    f16_split2(v.x, v.y, h0, l0);
    f16_split2(v.z, v.w, h1, l1);
    *reinterpret_cast<uint2*>(xh + i) = make_uint2(h0, h1);
    *reinterpret_cast<uint2*>(xl + i) = make_uint2(l0, l1);
}

// w [K][N] f32 -> u32 [K/2][N] pairs across k (low half = lower k)
__global__ void presplit_wpair(const float* __restrict__ w, uint32_t* __restrict__ wh,
                               uint32_t* __restrict__ wl, int K, int N) {
    int idx = blockIdx.x * blockDim.x + threadIdx.x;   // over (K/2)*(N/4)
    int kp = idx / (N >> 2);
    int n4 = (idx % (N >> 2)) * 4;
    if (kp >= (K >> 1)) return;
    const float* r0 = w + (size_t)(2 * kp) * N + n4;
    float4 a = *reinterpret_cast<const float4*>(r0);
    float4 b = *reinterpret_cast<const float4*>(r0 + N);
    uint32_t h[4], l[4];
    f16_split2(a.x, b.x, h[0], l[0]);
    f16_split2(a.y, b.y, h[1], l[1]);
    f16_split2(a.z, b.z, h[2], l[2]);
    f16_split2(a.w, b.w, h[3], l[3]);
    *reinterpret_cast<uint4*>(wh + (size_t)kp * N + n4) = make_uint4(h[0], h[1], h[2], h[3]);
    *reinterpret_cast<uint4*>(wl + (size_t)kp * N + n4) = make_uint4(l[0], l[1], l[2], l[3]);
}

// ---------------------------------------------------------------------------
// split-fp16 GEMM (round-13 proven structure), per-tile 3/2-term by column.
// C[M,N] = A[M,K] @ B[K,N]. A: row-major half hi/lo. B: pre-paired u32 [K/2][N].
// Block 128x128, BK=32, 256 thr (8 warps 2m x 4n), warp tile 64x32.
// mode 0: C fp32;  mode 1: C split-fp16 (Ch/Cl).
// 3-term iff bn < bn3limit: (Ah+Al)(Bh+Bl)-AlBl; else 2-term: Ah(Bh+Bl).
// ---------------------------------------------------------------------------
#define GAH (128 * 20)
#define GBH (16 * 136)

__global__ void __launch_bounds__(256, 2)
gemm_f16p_kernel(const __half* __restrict__ Ah_g, const __half* __restrict__ Al_g,
                 const uint32_t* __restrict__ Bh_g, const uint32_t* __restrict__ Bl_g,
                 float* __restrict__ Cf, __half* __restrict__ Ch, __half* __restrict__ Cl,
                 int M, int N, int K, int mode, int bn3limit) {
    __shared__ uint32_t Ah2[GAH], Al2[GAH], Bh2[GBH], Bl2[GBH];
    const uint32_t ah_s = smem_u32(Ah2);
    const uint32_t al_s = smem_u32(Al2);
    const uint32_t bh_s = smem_u32(Bh2);
    const uint32_t bl_s = smem_u32(Bl2);

    const int tid  = threadIdx.x;
    const int lane = tid & 31;
    const int warp = tid >> 5;
    const int g = lane >> 2;
    const int t = lane & 3;
    const int wm = warp >> 2;
    const int wn = warp & 3;
    const int bm = blockIdx.y * 128;
    const int bn = blockIdx.x * 128;
    const bool three = (bn < bn3limit);

    float acc[4][4][4];
#pragma unroll
    for (int i = 0; i < 4; i++)
#pragma unroll
        for (int j = 0; j < 4; j++)
#pragma unroll
            for (int v = 0; v < 4; v++) acc[i][j][v] = 0.f;

    for (int k0 = 0; k0 < K; k0 += 32) {
        // ---- issue cp.async staging ----
#pragma unroll
        for (int p = 0; p < 2; p++) {
            int idx = tid + p * 256;
            int r  = idx >> 2;
            int cu = (idx & 3) << 2;
            cp16(ah_s + (uint32_t)(r * 20 + cu) * 4u,
                 Ah_g + (size_t)(bm + r) * K + k0 + cu * 2);
            if (three)
                cp16(al_s + (uint32_t)(r * 20 + cu) * 4u,
                     Al_g + (size_t)(bm + r) * K + k0 + cu * 2);
        }
#pragma unroll
        for (int p = 0; p < 2; p++) {
            int idx = tid + p * 256;
            int kp = idx >> 5;
            int cu = (idx & 31) << 2;
            cp16(bh_s + (uint32_t)(kp * 136 + cu) * 4u,
                 Bh_g + (size_t)((k0 >> 1) + kp) * N + bn + cu);
            cp16(bl_s + (uint32_t)(kp * 136 + cu) * 4u,
                 Bl_g + (size_t)((k0 >> 1) + kp) * N + bn + cu);
        }
        CP_COMMIT();
        CP_WAIT0();
        __syncthreads();

        // ---- MMA phase ----
#pragma unroll
        for (int ks = 0; ks < 2; ks++) {
            const int kb2 = ks * 8;
            uint32_t afh[4][4], afl[4][4], bfh[4][2], bfl[4][2];
#pragma unroll
            for (int mt = 0; mt < 4; mt++) {
                int r0 = wm * 64 + mt * 16;
                int i0 = (r0 + g) * 20 + kb2 + t;
                int i1 = (r0 + 8 + g) * 20 + kb2 + t;
                afh[mt][0] = Ah2[i0];
                afh[mt][1] = Ah2[i1];
                afh[mt][2] = Ah2[i0 + 4];
                afh[mt][3] = Ah2[i1 + 4];
                if (three) {
                    afl[mt][0] = Al2[i0];
                    afl[mt][1] = Al2[i1];
                    afl[mt][2] = Al2[i0 + 4];
                    afl[mt][3] = Al2[i1 + 4];
                }
            }
#pragma unroll
            for (int nt = 0; nt < 4; nt++) {
                int c0 = wn * 32 + nt * 8;
                int i0 = (kb2 + t) * 136 + c0 + g;
                int i1 = (kb2 + t + 4) * 136 + c0 + g;
                bfh[nt][0] = Bh2[i0]; bfl[nt][0] = Bl2[i0];
                bfh[nt][1] = Bh2[i1]; bfl[nt][1] = Bl2[i1];
            }
            if (three) {
#pragma unroll
                for (int mt = 0; mt < 4; mt++)
#pragma unroll
                    for (int nt = 0; nt < 4; nt++)
                        mma3_f16(acc[mt][nt], afh[mt], afl[mt], bfh[nt], bfl[nt]);
            } else {
#pragma unroll
                for (int mt = 0; mt < 4; mt++)
#pragma unroll
                    for (int nt = 0; nt < 4; nt++) {
                        mma_f16(acc[mt][nt], afh[mt], bfl[nt]);
                        mma_f16(acc[mt][nt], afh[mt], bfh[nt]);
                    }
            }
        }
        __syncthreads();
    }

    // ---- epilogue ----
    if (mode == 0) {
#pragma unroll
        for (int mt = 0; mt < 4; mt++) {
            int row = bm + wm * 64 + mt * 16 + g;
#pragma unroll
            for (int nt = 0; nt < 4; nt++) {
                int col = bn + wn * 32 + nt * 8 + 2 * t;
                *reinterpret_cast<float2*>(Cf + (size_t)row * N + col) =
                    make_float2(acc[mt][nt][0], acc[mt][nt][1]);
                *reinterpret_cast<float2*>(Cf + (size_t)(row + 8) * N + col) =
                    make_float2(acc[mt][nt][2], acc[mt][nt][3]);
            }
        }
    } else {
#pragma unroll
        for (int mt = 0; mt < 4; mt++) {
            int row = bm + wm * 64 + mt * 16 + g;
#pragma unroll
            for (int nt = 0; nt < 4; nt++) {
                int col = bn + wn * 32 + nt * 8 + 2 * t;
                uint32_t hh, ll;
                f16_split2(acc[mt][nt][0], acc[mt][nt][1], hh, ll);
                *reinterpret_cast<uint32_t*>(Ch + (size_t)row * N + col) = hh;
                *reinterpret_cast<uint32_t*>(Cl + (size_t)row * N + col) = ll;
                f16_split2(acc[mt][nt][2], acc[mt][nt][3], hh, ll);
                *reinterpret_cast<uint32_t*>(Ch + (size_t)(row + 8) * N + col) = hh;
                *reinterpret_cast<uint32_t*>(Cl + (size_t)(row + 8) * N + col) = ll;
            }
        }
    }
}

// ---------------------------------------------------------------------------
// Flash attention. QK^T = 3-term; PV = 1-term (Ph*Vh, V hi-only).
// smem (u32): Kh2/Kl2 [64][36], Vh2 [32][72], Pr [64][36]
//   Pr = V-raw-hi staging ∪ P operand; Q staged via Vh2 (hi) + Pr (lo).
// NOTE: reference MULTIPLIES logits by sqrt(64)=8.
// ---------------------------------------------------------------------------
#define FKT (64 * 36)
#define FVT (32 * 72)
#define FLASH_SMEM ((2 * FKT + FVT + FKT) * 4)   // 36864 bytes

__global__ void __launch_bounds__(128, 4)
flash_f16p_kernel(const __half* __restrict__ Qh_g, const __half* __restrict__ Ql_g,
                  const __half* __restrict__ KVh_g, const __half* __restrict__ KVl_g,
                  __half* __restrict__ Oh) {
    extern __shared__ uint32_t sm[];
    uint32_t* Kh2 = sm;
    uint32_t* Kl2 = sm + FKT;
    uint32_t* Vh2 = sm + 2 * FKT;       // repacked V (pairs along j); also Qh staging
    uint32_t* Prh = Vh2 + FVT;          // V raw hi ∪ P operand; also Ql staging
    const uint32_t kh_s = smem_u32(Kh2);
    const uint32_t kl_s = smem_u32(Kl2);
    const uint32_t vh_s = smem_u32(Vh2);
    const uint32_t ph_s = smem_u32(Prh);

    const int tid  = threadIdx.x;
    const int lane = tid & 31;
    const int warp = tid >> 5;
    const int g = lane >> 2;
    const int t = lane & 3;
    const int wr = warp * 16;

    const int b  = blockIdx.z;
    const int h  = blockIdx.y;
    const int q0 = blockIdx.x * 64;

    const __half* Kbh = KVh_g + (size_t)b * 2048 * 2048 + h * 64;
    const __half* Kbl = KVl_g + (size_t)b * 2048 * 2048 + h * 64;

    auto load_K = [&](int j0) {
#pragma unroll
        for (int p = 0; p < 4; p++) {
            int idx = tid + p * 128;
            int r  = idx >> 3;
            int cu = (idx & 7) << 2;
            cp16(kh_s + (uint32_t)(r * 36 + cu) * 4u, Kbh + (size_t)(j0 + r) * 2048 + cu * 2);
            cp16(kl_s + (uint32_t)(r * 36 + cu) * 4u, Kbl + (size_t)(j0 + r) * 2048 + cu * 2);
        }
    };
    // V hi only, raw (pairs along d) into Pr
    auto load_V = [&](int j0) {
#pragma unroll
        for (int p = 0; p < 4; p++) {
            int idx = tid + p * 128;
            int r  = idx >> 3;
            int cu = (idx & 7) << 2;
            cp16(ph_s + (uint32_t)(r * 36 + cu) * 4u, Kbh + (size_t)(j0 + r) * 2048 + 1024 + cu * 2);
        }
    };

    // ---- prologue: K0 + Q (Qh->Vh2, Ql->Pr) ----
    load_K(0);
    {
        const __half* Qbh = Qh_g + (size_t)(b * 2048 + q0) * 1024 + h * 64;
        const __half* Qbl = Ql_g + (size_t)(b * 2048 + q0) * 1024 + h * 64;
#pragma unroll
        for (int p = 0; p < 4; p++) {
            int idx = tid + p * 128;
            int r  = idx >> 3;
            int cu = (idx & 7) << 2;
            cp16(vh_s + (uint32_t)(r * 36 + cu) * 4u, Qbh + (size_t)r * 1024 + cu * 2);
            cp16(ph_s + (uint32_t)(r * 36 + cu) * 4u, Qbl + (size_t)r * 1024 + cu * 2);
        }
    }
    CP_COMMIT();
    CP_WAIT0();
    __syncthreads();

    uint32_t qh[4][4], ql[4][4];
#pragma unroll
    for (int ks = 0; ks < 4; ks++) {
        int kb = ks * 8;
        int i0 = (wr + g) * 36 + kb + t;
        int i1 = (wr + 8 + g) * 36 + kb + t;
        qh[ks][0] = Vh2[i0];     ql[ks][0] = Prh[i0];
        qh[ks][1] = Vh2[i1];     ql[ks][1] = Prh[i1];
        qh[ks][2] = Vh2[i0 + 4]; ql[ks][2] = Prh[i0 + 4];
        qh[ks][3] = Vh2[i1 + 4]; ql[ks][3] = Prh[i1 + 4];
    }
    __syncthreads();          // Vh2/Pr free
    load_V(0); CP_COMMIT();   // V0 raw -> Pr

    float of[8][4];
#pragma unroll
    for (int i = 0; i < 8; i++)
#pragma unroll
        for (int v = 0; v < 4; v++) of[i][v] = 0.f;
    float m0 = -1e30f, m1 = -1e30f, l0 = 0.f, l1 = 0.f;

    for (int it = 0; it < 32; it++) {
        CP_WAIT0();          // V(it) raw (and K(it) from prev iter) complete
        __syncthreads();

        // ---- repack V raw hi (Pr, pairs along d) -> Vh2 (pairs along j) ----
#pragma unroll
        for (int p = 0; p < 8; p++) {
            int idx = tid + p * 128;         // 1024 (jp,dp) tasks
            int jp = idx >> 5;               // 0..31
            int dp = idx & 31;               // 0..31
            uint32_t X = Prh[(2 * jp) * 36 + dp];
            uint32_t Y = Prh[(2 * jp + 1) * 36 + dp];
            Vh2[jp * 72 + 2 * dp]     = __byte_perm(X, Y, 0x5410);
            Vh2[jp * 72 + 2 * dp + 1] = __byte_perm(X, Y, 0x7632);
        }
        __syncthreads();     // Vh2 ready; Pr free

        // ---- S = Q K^T (3-term) ----
        float sf[8][4];
#pragma unroll
        for (int nt = 0; nt < 8; nt++)
#pragma unroll
            for (int v = 0; v < 4; v++) sf[nt][v] = 0.f;
#pragma unroll
        for (int ks = 0; ks < 4; ks++) {
            int kb2 = ks * 8;
#pragma unroll
            for (int nt = 0; nt < 8; nt++) {
                int i0 = (nt * 8 + g) * 36 + kb2 + t;
                uint32_t bh[2] = { Kh2[i0], Kh2[i0 + 4] };
                uint32_t bl[2] = { Kl2[i0], Kl2[i0 + 4] };
                mma3_f16(sf[nt], qh[ks], ql[ks], bh, bl);
            }
        }
        __syncthreads();     // all warps done reading K
        if (it + 1 < 32) load_K((it + 1) * 64);
        CP_COMMIT();

        // ---- online softmax (x8 scale; rows g and g+8) ----
        float r0m = -1e30f, r1m = -1e30f;
#pragma unroll
        for (int nt = 0; nt < 8; nt++) {
            sf[nt][0] *= 8.f; sf[nt][1] *= 8.f; sf[nt][2] *= 8.f; sf[nt][3] *= 8.f;
            r0m = fmaxf(r0m, fmaxf(sf[nt][0], sf[nt][1]));
            r1m = fmaxf(r1m, fmaxf(sf[nt][2], sf[nt][3]));
        }
        r0m = fmaxf(r0m, __shfl_xor_sync(0xffffffffu, r0m, 1));
        r0m = fmaxf(r0m, __shfl_xor_sync(0xffffffffu, r0m, 2));
        r1m = fmaxf(r1m, __shfl_xor_sync(0xffffffffu, r1m, 1));
        r1m = fmaxf(r1m, __shfl_xor_sync(0xffffffffu, r1m, 2));

        float mn0 = fmaxf(m0, r0m), mn1 = fmaxf(m1, r1m);
        float cr0 = __expf(m0 - mn0), cr1 = __expf(m1 - mn1);
        float s0 = 0.f, s1 = 0.f;
#pragma unroll
        for (int nt = 0; nt < 8; nt++) {
            sf[nt][0] = __expf(sf[nt][0] - mn0);
            sf[nt][1] = __expf(sf[nt][1] - mn0);
            sf[nt][2] = __expf(sf[nt][2] - mn1);
            sf[nt][3] = __expf(sf[nt][3] - mn1);
            s0 += sf[nt][0] + sf[nt][1];
            s1 += sf[nt][2] + sf[nt][3];
        }
        s0 += __shfl_xor_sync(0xffffffffu, s0, 1);
        s0 += __shfl_xor_sync(0xffffffffu, s0, 2);
        s1 += __shfl_xor_sync(0xffffffffu, s1, 1);
        s1 += __shfl_xor_sync(0xffffffffu, s1, 2);
        l0 = l0 * cr0 + s0;  m0 = mn0;
        l1 = l1 * cr1 + s1;  m1 = mn1;
#pragma unroll
        for (int dt = 0; dt < 8; dt++) {
            of[dt][0] *= cr0; of[dt][1] *= cr0;
            of[dt][2] *= cr1; of[dt][3] *= cr1;
        }

        // ---- stage P fp16 hi-only into Pr (per-warp-private rows) ----
#pragma unroll
        for (int nt = 0; nt < 8; nt++) {
            Prh[(wr + g) * 36 + nt * 4 + t]     = f16_pack2(sf[nt][0], sf[nt][1]);
            Prh[(wr + 8 + g) * 36 + nt * 4 + t] = f16_pack2(sf[nt][2], sf[nt][3]);
        }
        __syncwarp();

        // ---- O += P V (1-term: Ph*Vh) ----
#pragma unroll
        for (int ks = 0; ks < 4; ks++) {
            int kb2 = ks * 8;
            int i0 = (wr + g) * 36 + kb2 + t;
            int i1 = (wr + 8 + g) * 36 + kb2 + t;
            uint32_t ah[4] = { Prh[i0], Prh[i1], Prh[i0 + 4], Prh[i1 + 4] };
#pragma unroll
            for (int nt = 0; nt < 8; nt++) {
                int j0i = (kb2 + t) * 72 + nt * 8 + g;
                int j1i = (kb2 + t + 4) * 72 + nt * 8 + g;
                uint32_t bh[2] = { Vh2[j0i], Vh2[j1i] };
                mma_f16(of[nt], ah, bh);
            }
        }
        __syncthreads();     // all warps done with Pr + Vh2
        if (it + 1 < 32) load_V((it + 1) * 64);   // prefetch next V raw into Pr
        CP_COMMIT();
    }

    // ---- epilogue: ao hi-only fp16 ----
    float inv0 = 1.f / l0, inv1 = 1.f / l1;
    int row0 = b * 2048 + q0 + wr + g;
#pragma unroll
    for (int nt = 0; nt < 8; nt++) {
        int col = h * 64 + nt * 8 + 2 * t;
        *reinterpret_cast<uint32_t*>(Oh + (size_t)row0 * 1024 + col) =
            f16_pack2(of[nt][0] * inv0, of[nt][1] * inv0);
        *reinterpret_cast<uint32_t*>(Oh + (size_t)(row0 + 8) * 1024 + col) =
            f16_pack2(of[nt][2] * inv1, of[nt][3] * inv1);
    }
}

// ---------------------------------------------------------------------------
extern "C" void kernel_launch(void* const* d_in, const int* in_sizes, int n_in,
                              void* d_out, int out_size) {
    const float* x     = (const float*)d_in[0];   // [2,2048,1024]
    const float* w_q   = (const float*)d_in[1];   // [1024,1024]
    const float* w_vk  = (const float*)d_in[2];   // [1024,2048]
    const float* w_out = (const float*)d_in[3];   // [1024,1024]
    float* out = (float*)d_out;                   // [2,2048,1024]

    __half *xh, *xl, *qh, *ql, *kvh, *kvl, *aoh;
    uint32_t *wqh, *wql, *wvkh, *wvkl, *woh, *wol;
    cudaGetSymbolAddress((void**)&xh,  g_xh);   cudaGetSymbolAddress((void**)&xl,  g_xl);
    cudaGetSymbolAddress((void**)&wqh, g_wq_h); cudaGetSymbolAddress((void**)&wql, g_wq_l);
    cudaGetSymbolAddress((void**)&wvkh, g_wvk_h); cudaGetSymbolAddress((void**)&wvkl, g_wvk_l);
    cudaGetSymbolAddress((void**)&woh, g_wo_h); cudaGetSymbolAddress((void**)&wol, g_wo_l);
    cudaGetSymbolAddress((void**)&qh,  g_qh);   cudaGetSymbolAddress((void**)&ql,  g_ql);
    cudaGetSymbolAddress((void**)&kvh, g_kvh);  cudaGetSymbolAddress((void**)&kvl, g_kvl);
    cudaGetSymbolAddress((void**)&aoh, g_aoh);

    cudaFuncSetAttribute(flash_f16p_kernel,
                         cudaFuncAttributeMaxDynamicSharedMemorySize, FLASH_SMEM);

    // presplit (once per launch; cheap)
    presplit_plain<<<4096, 256>>>(x, xh, xl, 4096 * 1024);
    presplit_wpair<<<512,  256>>>(w_q,   wqh,  wql,  1024, 1024);
    presplit_wpair<<<1024, 256>>>(w_vk,  wvkh, wvkl, 1024, 2048);
    presplit_wpair<<<512,  256>>>(w_out, woh,  wol,  1024, 1024);

    // Q = x @ w_q  -> split fp16 (3-term everywhere)
    gemm_f16p_kernel<<<dim3(8, 32), 256>>>(xh, xl, wqh, wql,
                                           nullptr, qh, ql, 4096, 1024, 1024, 1, 1 << 30);
    // KV = x @ w_vk -> split fp16 (K cols 3-term, V cols 2-term)
    gemm_f16p_kernel<<<dim3(16, 32), 256>>>(xh, xl, wvkh, wvkl,
                                            nullptr, kvh, kvl, 4096, 2048, 1024, 1, 1024);
    // attention -> hi-only fp16 ao (QK 3-term, PV 1-term with V hi-only)
    flash_f16p_kernel<<<dim3(32, 16, 2), 128, FLASH_SMEM>>>(qh, ql, kvh, kvl, aoh);
    // out = ao @ w_out -> fp32 (2-term: aoh * (Wh + Wl))
    gemm_f16p_kernel<<<dim3(8, 32), 256>>>(aoh, nullptr, woh, wol,
                                           out, nullptr, nullptr, 4096, 1024, 1024, 0, 0);
}